// round 11
// baseline (speedup 1.0000x reference)
#include <cuda_runtime.h>

#define N_NODES 50000
#define N_EDGES 800000
#define DIM 64
#define NCHUNK 49            // ceil(50000/1024)

// Scratch (device globals — no allocation allowed). BSS zero-init at load.
// g_deg is re-zeroed inside k_scan_chain each run; chain flags use epoch
// counters (monotonic) so no reset is needed across graph replays.
__device__ int   g_deg[N_NODES];
__device__ int   g_row[N_NODES + 1];
__device__ int   g_cur[N_NODES];
__device__ int   g_col[N_EDGES];
__device__ float g_x1[N_NODES * DIM];
__device__ float g_agg[N_NODES * DIM];
__device__ int   g_chain_val[NCHUNK];
__device__ int   g_chain_flag[NCHUNK];   // epoch counts, never reset

// ------------------------------------------------------------------ hist
__global__ void k_hist(const int* __restrict__ ei) {
    int e = blockIdx.x * blockDim.x + threadIdx.x;
    if (e < N_EDGES) atomicAdd(&g_deg[ei[N_EDGES + e]], 1);
}

// -------------------- chained exclusive scan (one kernel, 49 blocks) -----
// Block b scans its 1024-chunk, waits for predecessor's running total via an
// epoch flag (flag[b] == number of completed replays for block b), then
// publishes its own. All blocks co-resident (49 << 148 SMs) => no deadlock.
__global__ void __launch_bounds__(1024) k_scan_chain() {
    __shared__ int wsum[32];
    __shared__ int s_base;
    int t = threadIdx.x, lane = t & 31, wid = t >> 5;
    int b = blockIdx.x;
    int i = b * 1024 + t;
    int v = 0;
    if (i < N_NODES) { v = g_deg[i]; g_deg[i] = 0; }
    int sc = v;
    #pragma unroll
    for (int off = 1; off < 32; off <<= 1) {
        int n = __shfl_up_sync(0xffffffffu, sc, off);
        if (lane >= off) sc += n;
    }
    if (lane == 31) wsum[wid] = sc;
    __syncthreads();
    if (wid == 0) {
        int w = wsum[lane];
        #pragma unroll
        for (int off = 1; off < 32; off <<= 1) {
            int n = __shfl_up_sync(0xffffffffu, w, off);
            if (lane >= off) w += n;
        }
        wsum[lane] = w;
    }
    __syncthreads();
    int wpre  = (wid > 0) ? wsum[wid - 1] : 0;
    int total = wsum[31];
    if (t == 0) {
        int E = g_chain_flag[b];           // this replay's epoch for block b
        int base = 0;
        if (b > 0) {
            while (atomicAdd(&g_chain_flag[b - 1], 0) <= E) {}
            __threadfence();
            base = g_chain_val[b - 1];
        }
        g_chain_val[b] = base + total;
        __threadfence();
        atomicExch(&g_chain_flag[b], E + 1);
        s_base = base;
    }
    __syncthreads();
    int ex = s_base + wpre + sc - v;
    if (i < N_NODES) { g_row[i] = ex; g_cur[i] = ex; }
    if (i == 0) g_row[N_NODES] = N_EDGES;
}

// --------------------------------------------------------------- scatter
__global__ void k_scatter(const int* __restrict__ ei) {
    int e = blockIdx.x * blockDim.x + threadIdx.x;
    if (e < N_EDGES) {
        int d = ei[N_EDGES + e];
        int p = atomicAdd(&g_cur[d], 1);
        g_col[p] = ei[e];
    }
}

// ------------------------------------------------------------- aggregation
// One warp per node: mean over {self} ∪ in-neighbors -> g_agg.
// (Measured: 22.5us, occ 82%, L2 40% — keep as-is.)
__global__ void k_agg(const float* __restrict__ x) {
    int w    = (blockIdx.x * blockDim.x + threadIdx.x) >> 5;
    int lane = threadIdx.x & 31;
    if (w >= N_NODES) return;

    const float2* xs = (const float2*)x;
    float2 v = xs[w * 32 + lane];
    float a0 = v.x, a1 = v.y;

    int start = g_row[w];
    int cnt   = g_row[w + 1] - start;

    for (int base = 0; base < cnt; base += 32) {
        int rem = cnt - base;
        int m   = rem < 32 ? rem : 32;
        int c   = (lane < m) ? g_col[start + base + lane] : 0;
        int t = 0;
        for (; t + 4 <= m; t += 4) {
            int s0 = __shfl_sync(0xffffffffu, c, t);
            int s1 = __shfl_sync(0xffffffffu, c, t + 1);
            int s2 = __shfl_sync(0xffffffffu, c, t + 2);
            int s3 = __shfl_sync(0xffffffffu, c, t + 3);
            float2 v0 = xs[s0 * 32 + lane];
            float2 v1 = xs[s1 * 32 + lane];
            float2 v2 = xs[s2 * 32 + lane];
            float2 v3 = xs[s3 * 32 + lane];
            a0 += v0.x; a1 += v0.y;
            a0 += v1.x; a1 += v1.y;
            a0 += v2.x; a1 += v2.y;
            a0 += v3.x; a1 += v3.y;
        }
        for (; t < m; t++) {
            int s = __shfl_sync(0xffffffffu, c, t);
            float2 vv = xs[s * 32 + lane];
            a0 += vv.x; a1 += vv.y;
        }
    }
    float inv = 1.0f / (float)(cnt + 1);
    ((float2*)g_agg)[w * 32 + lane] = make_float2(a0 * inv, a1 * inv);
}

// ------------------------------------------------------------------- GEMM
// out[n] = relu( agg[n] @ Wl + bl + x[n] @ Wr )
// (Measured: 6.5us — keep as-is.)
__global__ void __launch_bounds__(256, 2) k_mm(const float* __restrict__ x,
                                               const float* __restrict__ Wl,
                                               const float* __restrict__ bl,
                                               const float* __restrict__ Wr,
                                               float* __restrict__ out) {
    extern __shared__ float sm[];
    float* wl_s = sm;                 // [64][64]
    float* wr_s = sm + 4096;          // [64][64]
    float* a_s  = sm + 8192;          // [64 k][128 node]
    float* x_s  = sm + 16384;         // [64 k][128 node]

    int tid   = threadIdx.x;
    int node0 = blockIdx.x * 128;

    for (int i = tid; i < DIM * DIM / 4; i += 256) {
        ((float4*)wl_s)[i] = ((const float4*)Wl)[i];
        ((float4*)wr_s)[i] = ((const float4*)Wr)[i];
    }
    {
        int nl = tid & 127;
        int kh = (tid >> 7) * 32;
        int node = node0 + nl;
        bool ok = node < N_NODES;
        const float4* xr = (const float4*)(x     + node * DIM + kh);
        const float4* ar = (const float4*)(g_agg + node * DIM + kh);
        #pragma unroll
        for (int j = 0; j < 8; j++) {
            float4 vx = ok ? xr[j] : make_float4(0.f, 0.f, 0.f, 0.f);
            float4 va = ok ? ar[j] : make_float4(0.f, 0.f, 0.f, 0.f);
            int k = kh + j * 4;
            x_s[(k + 0) * 128 + nl] = vx.x;
            x_s[(k + 1) * 128 + nl] = vx.y;
            x_s[(k + 2) * 128 + nl] = vx.z;
            x_s[(k + 3) * 128 + nl] = vx.w;
            a_s[(k + 0) * 128 + nl] = va.x;
            a_s[(k + 1) * 128 + nl] = va.y;
            a_s[(k + 2) * 128 + nl] = va.z;
            a_s[(k + 3) * 128 + nl] = va.w;
        }
    }
    __syncthreads();

    int nrow = (tid >> 3) << 2;   // 0,4,...,124
    int fcol = (tid & 7) << 3;    // 0,8,...,56

    float acc[4][8];
    #pragma unroll
    for (int i = 0; i < 4; i++)
        #pragma unroll
        for (int f = 0; f < 8; f++) acc[i][f] = 0.f;

    #pragma unroll 8
    for (int kk = 0; kk < DIM; kk++) {
        float wlv[8], wrv[8];
        *(float4*)&wlv[0] = *(const float4*)&wl_s[kk * DIM + fcol];
        *(float4*)&wlv[4] = *(const float4*)&wl_s[kk * DIM + fcol + 4];
        *(float4*)&wrv[0] = *(const float4*)&wr_s[kk * DIM + fcol];
        *(float4*)&wrv[4] = *(const float4*)&wr_s[kk * DIM + fcol + 4];
        #pragma unroll
        for (int i = 0; i < 4; i++) {
            float av = a_s[kk * 128 + nrow + i];
            float xv = x_s[kk * 128 + nrow + i];
            #pragma unroll
            for (int f = 0; f < 8; f++)
                acc[i][f] += av * wlv[f] + xv * wrv[f];
        }
    }

    float bv[8];
    *(float4*)&bv[0] = *(const float4*)(bl + fcol);
    *(float4*)&bv[4] = *(const float4*)(bl + fcol + 4);

    #pragma unroll
    for (int i = 0; i < 4; i++) {
        int node = node0 + nrow + i;
        if (node < N_NODES) {
            float4 o0, o1;
            o0.x = fmaxf(acc[i][0] + bv[0], 0.f);
            o0.y = fmaxf(acc[i][1] + bv[1], 0.f);
            o0.z = fmaxf(acc[i][2] + bv[2], 0.f);
            o0.w = fmaxf(acc[i][3] + bv[3], 0.f);
            o1.x = fmaxf(acc[i][4] + bv[4], 0.f);
            o1.y = fmaxf(acc[i][5] + bv[5], 0.f);
            o1.z = fmaxf(acc[i][6] + bv[6], 0.f);
            o1.w = fmaxf(acc[i][7] + bv[7], 0.f);
            *(float4*)(out + node * DIM + fcol)     = o0;
            *(float4*)(out + node * DIM + fcol + 4) = o1;
        }
    }
}

// ------------------------------------------------------------------ launch
extern "C" void kernel_launch(void* const* d_in, const int* in_sizes, int n_in,
                              void* d_out, int out_size) {
    const float* x   = (const float*)d_in[0];
    const int*   ei  = (const int*)  d_in[1];
    const float* Wl0 = (const float*)d_in[2];
    const float* bl0 = (const float*)d_in[3];
    const float* Wr0 = (const float*)d_in[4];
    const float* Wl1 = (const float*)d_in[5];
    const float* bl1 = (const float*)d_in[6];
    const float* Wr1 = (const float*)d_in[7];
    float* out = (float*)d_out;

    const int MM_SMEM = 24576 * sizeof(float);   // 96 KB dynamic
    cudaFuncSetAttribute(k_mm, cudaFuncAttributeMaxDynamicSharedMemorySize, MM_SMEM);

    int agg_blocks = (N_NODES * 32 + 255) / 256;
    int mm_blocks  = (N_NODES + 127) / 128;

    k_hist      <<<(N_EDGES + 255) / 256, 256>>>(ei);                  // 1
    k_scan_chain<<<NCHUNK, 1024>>>();                                  // 2
    k_scatter   <<<(N_EDGES + 255) / 256, 256>>>(ei);                  // 3
    k_agg       <<<agg_blocks, 256>>>(x);                              // 4 <- ncu
    k_mm        <<<mm_blocks, 256, MM_SMEM>>>(x, Wl0, bl0, Wr0, g_x1); // 5
    k_agg       <<<agg_blocks, 256>>>(g_x1);                           // 6
    k_mm        <<<mm_blocks, 256, MM_SMEM>>>(g_x1, Wl1, bl1, Wr1, out);// 7
}

// round 12
// speedup vs baseline: 1.0066x; 1.0066x over previous
#include <cuda_runtime.h>

#define N_NODES 50000
#define N_EDGES 800000
#define DIM 64
#define NCHUNK 49            // ceil(50000/1024)

// Scratch (device globals — no allocation allowed). BSS zero-init at load.
// g_deg is re-zeroed inside k_scan_chain each run; chain flags use epoch
// counters (monotonic) so no reset is needed across graph replays.
__device__ int   g_deg[N_NODES];
__device__ int   g_row[N_NODES + 1];
__device__ int   g_cur[N_NODES];
__device__ int   g_col[N_EDGES];
__device__ float g_x1[N_NODES * DIM];
__device__ float g_agg[N_NODES * DIM];
__device__ int   g_chain_val[NCHUNK];
__device__ int   g_chain_flag[NCHUNK];   // epoch counts, never reset

// ------------------------------------------------------------------ hist
// 4 edges per thread via int4 (N_EDGES % 4 == 0).
__global__ void k_hist(const int* __restrict__ ei) {
    int t = blockIdx.x * blockDim.x + threadIdx.x;
    if (t < N_EDGES / 4) {
        int4 d = ((const int4*)(ei + N_EDGES))[t];
        atomicAdd(&g_deg[d.x], 1);
        atomicAdd(&g_deg[d.y], 1);
        atomicAdd(&g_deg[d.z], 1);
        atomicAdd(&g_deg[d.w], 1);
    }
}

// -------------------- chained exclusive scan (one kernel, 49 blocks) -----
// Block b scans its 1024-chunk, waits for predecessor's running total via an
// epoch flag (flag[b] == number of completed replays for block b), then
// publishes its own. All blocks co-resident (49 << 148 SMs) => no deadlock.
__global__ void __launch_bounds__(1024) k_scan_chain() {
    __shared__ int wsum[32];
    __shared__ int s_base;
    int t = threadIdx.x, lane = t & 31, wid = t >> 5;
    int b = blockIdx.x;
    int i = b * 1024 + t;
    int v = 0;
    if (i < N_NODES) { v = g_deg[i]; g_deg[i] = 0; }
    int sc = v;
    #pragma unroll
    for (int off = 1; off < 32; off <<= 1) {
        int n = __shfl_up_sync(0xffffffffu, sc, off);
        if (lane >= off) sc += n;
    }
    if (lane == 31) wsum[wid] = sc;
    __syncthreads();
    if (wid == 0) {
        int w = wsum[lane];
        #pragma unroll
        for (int off = 1; off < 32; off <<= 1) {
            int n = __shfl_up_sync(0xffffffffu, w, off);
            if (lane >= off) w += n;
        }
        wsum[lane] = w;
    }
    __syncthreads();
    int wpre  = (wid > 0) ? wsum[wid - 1] : 0;
    int total = wsum[31];
    if (t == 0) {
        int E = g_chain_flag[b];           // this replay's epoch for block b
        int base = 0;
        if (b > 0) {
            while (atomicAdd(&g_chain_flag[b - 1], 0) <= E) {}
            __threadfence();
            base = g_chain_val[b - 1];
        }
        g_chain_val[b] = base + total;
        __threadfence();
        atomicExch(&g_chain_flag[b], E + 1);
        s_base = base;
    }
    __syncthreads();
    int ex = s_base + wpre + sc - v;
    if (i < N_NODES) { g_row[i] = ex; g_cur[i] = ex; }
    if (i == 0) g_row[N_NODES] = N_EDGES;
}

// --------------------------------------------------------------- scatter
// 4 edges per thread via int4.
__global__ void k_scatter(const int* __restrict__ ei) {
    int t = blockIdx.x * blockDim.x + threadIdx.x;
    if (t < N_EDGES / 4) {
        int4 s = ((const int4*)ei)[t];
        int4 d = ((const int4*)(ei + N_EDGES))[t];
        g_col[atomicAdd(&g_cur[d.x], 1)] = s.x;
        g_col[atomicAdd(&g_cur[d.y], 1)] = s.y;
        g_col[atomicAdd(&g_cur[d.z], 1)] = s.z;
        g_col[atomicAdd(&g_cur[d.w], 1)] = s.w;
    }
}

// ------------------------------------------------------------- aggregation
// One warp per node: mean over {self} ∪ in-neighbors -> g_agg.
// (Measured: 22.5us, occ 82%, ~80% of L2 roofline — keep as-is.)
__global__ void k_agg(const float* __restrict__ x) {
    int w    = (blockIdx.x * blockDim.x + threadIdx.x) >> 5;
    int lane = threadIdx.x & 31;
    if (w >= N_NODES) return;

    const float2* xs = (const float2*)x;
    float2 v = xs[w * 32 + lane];
    float a0 = v.x, a1 = v.y;

    int start = g_row[w];
    int cnt   = g_row[w + 1] - start;

    for (int base = 0; base < cnt; base += 32) {
        int rem = cnt - base;
        int m   = rem < 32 ? rem : 32;
        int c   = (lane < m) ? g_col[start + base + lane] : 0;
        int t = 0;
        for (; t + 4 <= m; t += 4) {
            int s0 = __shfl_sync(0xffffffffu, c, t);
            int s1 = __shfl_sync(0xffffffffu, c, t + 1);
            int s2 = __shfl_sync(0xffffffffu, c, t + 2);
            int s3 = __shfl_sync(0xffffffffu, c, t + 3);
            float2 v0 = xs[s0 * 32 + lane];
            float2 v1 = xs[s1 * 32 + lane];
            float2 v2 = xs[s2 * 32 + lane];
            float2 v3 = xs[s3 * 32 + lane];
            a0 += v0.x; a1 += v0.y;
            a0 += v1.x; a1 += v1.y;
            a0 += v2.x; a1 += v2.y;
            a0 += v3.x; a1 += v3.y;
        }
        for (; t < m; t++) {
            int s = __shfl_sync(0xffffffffu, c, t);
            float2 vv = xs[s * 32 + lane];
            a0 += vv.x; a1 += vv.y;
        }
    }
    float inv = 1.0f / (float)(cnt + 1);
    ((float2*)g_agg)[w * 32 + lane] = make_float2(a0 * inv, a1 * inv);
}

// ------------------------------------------------------------------- GEMM
// out[n] = relu( agg[n] @ Wl + bl + x[n] @ Wr )
// (Measured: 6.5us — keep as-is.)
__global__ void __launch_bounds__(256, 2) k_mm(const float* __restrict__ x,
                                               const float* __restrict__ Wl,
                                               const float* __restrict__ bl,
                                               const float* __restrict__ Wr,
                                               float* __restrict__ out) {
    extern __shared__ float sm[];
    float* wl_s = sm;                 // [64][64]
    float* wr_s = sm + 4096;          // [64][64]
    float* a_s  = sm + 8192;          // [64 k][128 node]
    float* x_s  = sm + 16384;         // [64 k][128 node]

    int tid   = threadIdx.x;
    int node0 = blockIdx.x * 128;

    for (int i = tid; i < DIM * DIM / 4; i += 256) {
        ((float4*)wl_s)[i] = ((const float4*)Wl)[i];
        ((float4*)wr_s)[i] = ((const float4*)Wr)[i];
    }
    {
        int nl = tid & 127;
        int kh = (tid >> 7) * 32;
        int node = node0 + nl;
        bool ok = node < N_NODES;
        const float4* xr = (const float4*)(x     + node * DIM + kh);
        const float4* ar = (const float4*)(g_agg + node * DIM + kh);
        #pragma unroll
        for (int j = 0; j < 8; j++) {
            float4 vx = ok ? xr[j] : make_float4(0.f, 0.f, 0.f, 0.f);
            float4 va = ok ? ar[j] : make_float4(0.f, 0.f, 0.f, 0.f);
            int k = kh + j * 4;
            x_s[(k + 0) * 128 + nl] = vx.x;
            x_s[(k + 1) * 128 + nl] = vx.y;
            x_s[(k + 2) * 128 + nl] = vx.z;
            x_s[(k + 3) * 128 + nl] = vx.w;
            a_s[(k + 0) * 128 + nl] = va.x;
            a_s[(k + 1) * 128 + nl] = va.y;
            a_s[(k + 2) * 128 + nl] = va.z;
            a_s[(k + 3) * 128 + nl] = va.w;
        }
    }
    __syncthreads();

    int nrow = (tid >> 3) << 2;   // 0,4,...,124
    int fcol = (tid & 7) << 3;    // 0,8,...,56

    float acc[4][8];
    #pragma unroll
    for (int i = 0; i < 4; i++)
        #pragma unroll
        for (int f = 0; f < 8; f++) acc[i][f] = 0.f;

    #pragma unroll 8
    for (int kk = 0; kk < DIM; kk++) {
        float wlv[8], wrv[8];
        *(float4*)&wlv[0] = *(const float4*)&wl_s[kk * DIM + fcol];
        *(float4*)&wlv[4] = *(const float4*)&wl_s[kk * DIM + fcol + 4];
        *(float4*)&wrv[0] = *(const float4*)&wr_s[kk * DIM + fcol];
        *(float4*)&wrv[4] = *(const float4*)&wr_s[kk * DIM + fcol + 4];
        #pragma unroll
        for (int i = 0; i < 4; i++) {
            float av = a_s[kk * 128 + nrow + i];
            float xv = x_s[kk * 128 + nrow + i];
            #pragma unroll
            for (int f = 0; f < 8; f++)
                acc[i][f] += av * wlv[f] + xv * wrv[f];
        }
    }

    float bv[8];
    *(float4*)&bv[0] = *(const float4*)(bl + fcol);
    *(float4*)&bv[4] = *(const float4*)(bl + fcol + 4);

    #pragma unroll
    for (int i = 0; i < 4; i++) {
        int node = node0 + nrow + i;
        if (node < N_NODES) {
            float4 o0, o1;
            o0.x = fmaxf(acc[i][0] + bv[0], 0.f);
            o0.y = fmaxf(acc[i][1] + bv[1], 0.f);
            o0.z = fmaxf(acc[i][2] + bv[2], 0.f);
            o0.w = fmaxf(acc[i][3] + bv[3], 0.f);
            o1.x = fmaxf(acc[i][4] + bv[4], 0.f);
            o1.y = fmaxf(acc[i][5] + bv[5], 0.f);
            o1.z = fmaxf(acc[i][6] + bv[6], 0.f);
            o1.w = fmaxf(acc[i][7] + bv[7], 0.f);
            *(float4*)(out + node * DIM + fcol)     = o0;
            *(float4*)(out + node * DIM + fcol + 4) = o1;
        }
    }
}

// ------------------------------------------------------------------ launch
extern "C" void kernel_launch(void* const* d_in, const int* in_sizes, int n_in,
                              void* d_out, int out_size) {
    const float* x   = (const float*)d_in[0];
    const int*   ei  = (const int*)  d_in[1];
    const float* Wl0 = (const float*)d_in[2];
    const float* bl0 = (const float*)d_in[3];
    const float* Wr0 = (const float*)d_in[4];
    const float* Wl1 = (const float*)d_in[5];
    const float* bl1 = (const float*)d_in[6];
    const float* Wr1 = (const float*)d_in[7];
    float* out = (float*)d_out;

    const int MM_SMEM = 24576 * sizeof(float);   // 96 KB dynamic
    cudaFuncSetAttribute(k_mm, cudaFuncAttributeMaxDynamicSharedMemorySize, MM_SMEM);

    int agg_blocks  = (N_NODES * 32 + 255) / 256;
    int mm_blocks   = (N_NODES + 127) / 128;
    int edge4_blocks = (N_EDGES / 4 + 255) / 256;

    k_hist      <<<edge4_blocks, 256>>>(ei);                           // 1
    k_scan_chain<<<NCHUNK, 1024>>>();                                  // 2
    k_scatter   <<<edge4_blocks, 256>>>(ei);                           // 3
    k_agg       <<<agg_blocks, 256>>>(x);                              // 4 <- ncu
    k_mm        <<<mm_blocks, 256, MM_SMEM>>>(x, Wl0, bl0, Wr0, g_x1); // 5
    k_agg       <<<agg_blocks, 256>>>(g_x1);                           // 6
    k_mm        <<<mm_blocks, 256, MM_SMEM>>>(g_x1, Wl1, bl1, Wr1, out);// 7
}

// round 13
// speedup vs baseline: 1.1724x; 1.1648x over previous
#include <cuda_runtime.h>

#define N_NODES 50000
#define N_EDGES 800000
#define DIM 64
#define NCHUNK 49            // ceil(50000/1024)
#define PAD 65               // smem row pitch (floats), conflict-free

// Scratch (device globals — no allocation allowed). BSS zero-init at load.
// g_deg is re-zeroed inside k_scan_chain each run; chain flags use epoch
// counters (monotonic) so no reset is needed across graph replays.
__device__ int   g_deg[N_NODES];
__device__ int   g_row[N_NODES + 1];
__device__ int   g_cur[N_NODES];
__device__ int   g_col[N_EDGES];
__device__ float g_x1[N_NODES * DIM];
__device__ int   g_chain_val[NCHUNK];
__device__ int   g_chain_flag[NCHUNK];   // epoch counts, never reset

// ------------------------------------------------------------------ hist
// 4 edges per thread via int4 (N_EDGES % 4 == 0).
__global__ void k_hist(const int* __restrict__ ei) {
    int t = blockIdx.x * blockDim.x + threadIdx.x;
    if (t < N_EDGES / 4) {
        int4 d = ((const int4*)(ei + N_EDGES))[t];
        atomicAdd(&g_deg[d.x], 1);
        atomicAdd(&g_deg[d.y], 1);
        atomicAdd(&g_deg[d.z], 1);
        atomicAdd(&g_deg[d.w], 1);
    }
}

// -------------------- chained exclusive scan (one kernel, 49 blocks) -----
// Block b scans its 1024-chunk, waits for predecessor's running total via an
// epoch flag, then publishes its own. Forward-progress only (no barrier).
__global__ void __launch_bounds__(1024) k_scan_chain() {
    __shared__ int wsum[32];
    __shared__ int s_base;
    int t = threadIdx.x, lane = t & 31, wid = t >> 5;
    int b = blockIdx.x;
    int i = b * 1024 + t;
    int v = 0;
    if (i < N_NODES) { v = g_deg[i]; g_deg[i] = 0; }
    int sc = v;
    #pragma unroll
    for (int off = 1; off < 32; off <<= 1) {
        int n = __shfl_up_sync(0xffffffffu, sc, off);
        if (lane >= off) sc += n;
    }
    if (lane == 31) wsum[wid] = sc;
    __syncthreads();
    if (wid == 0) {
        int w = wsum[lane];
        #pragma unroll
        for (int off = 1; off < 32; off <<= 1) {
            int n = __shfl_up_sync(0xffffffffu, w, off);
            if (lane >= off) w += n;
        }
        wsum[lane] = w;
    }
    __syncthreads();
    int wpre  = (wid > 0) ? wsum[wid - 1] : 0;
    int total = wsum[31];
    if (t == 0) {
        int E = g_chain_flag[b];           // this replay's epoch for block b
        int base = 0;
        if (b > 0) {
            while (atomicAdd(&g_chain_flag[b - 1], 0) <= E) {}
            __threadfence();
            base = g_chain_val[b - 1];
        }
        g_chain_val[b] = base + total;
        __threadfence();
        atomicExch(&g_chain_flag[b], E + 1);
        s_base = base;
    }
    __syncthreads();
    int ex = s_base + wpre + sc - v;
    if (i < N_NODES) { g_row[i] = ex; g_cur[i] = ex; }
    if (i == 0) g_row[N_NODES] = N_EDGES;
}

// --------------------------------------------------------------- scatter
// 4 edges per thread via int4.
__global__ void k_scatter(const int* __restrict__ ei) {
    int t = blockIdx.x * blockDim.x + threadIdx.x;
    if (t < N_EDGES / 4) {
        int4 s = ((const int4*)ei)[t];
        int4 d = ((const int4*)(ei + N_EDGES))[t];
        g_col[atomicAdd(&g_cur[d.x], 1)] = s.x;
        g_col[atomicAdd(&g_cur[d.y], 1)] = s.y;
        g_col[atomicAdd(&g_cur[d.z], 1)] = s.z;
        g_col[atomicAdd(&g_cur[d.w], 1)] = s.w;
    }
}

// ------------- fused layer: aggregation + GEMM + bias + relu --------------
// Block owns 128 nodes, 512 threads = 16 warps. (Exact code of the config
// that measured wall=1325us.)
__global__ void __launch_bounds__(512, 2) k_layer(const float* __restrict__ x,
                                                  const float* __restrict__ Wl,
                                                  const float* __restrict__ bl,
                                                  const float* __restrict__ Wr,
                                                  float* __restrict__ out) {
    extern __shared__ float sm[];
    float* wl_s = sm;                     // [64*64]
    float* wr_s = sm + 4096;              // [64*64]
    float* a_s  = sm + 8192;              // [128][PAD]
    float* x_s  = sm + 8192 + 128 * PAD;  // [128][PAD]

    const int tid   = threadIdx.x;
    const int lane  = tid & 31;
    const int w     = tid >> 5;           // warp 0..15
    const int node0 = blockIdx.x * 128;

    for (int i = tid; i < DIM * DIM / 4; i += 512) {
        ((float4*)wl_s)[i] = ((const float4*)Wl)[i];
        ((float4*)wr_s)[i] = ((const float4*)Wr)[i];
    }
    {
        int nl = tid & 127;
        int kh = (tid >> 7) * 16;
        int node = node0 + nl;
        if (node < N_NODES) {
            const float4* xr = (const float4*)(x + node * DIM + kh);
            #pragma unroll
            for (int j = 0; j < 4; j++) {
                float4 v = xr[j];
                int k = kh + j * 4;
                x_s[nl * PAD + k + 0] = v.x;
                x_s[nl * PAD + k + 1] = v.y;
                x_s[nl * PAD + k + 2] = v.z;
                x_s[nl * PAD + k + 3] = v.w;
            }
        }
    }
    __syncthreads();

    // aggregation: warp w -> nodes w*8 .. w*8+7 (mean incl. self)
    const float2* xs = (const float2*)x;
    #pragma unroll 1
    for (int q = 0; q < 8; q++) {
        int nl = w * 8 + q;
        int n  = node0 + nl;
        if (n >= N_NODES) break;
        float a0 = x_s[nl * PAD + 2 * lane];
        float a1 = x_s[nl * PAD + 2 * lane + 1];
        int start = g_row[n];
        int cnt   = g_row[n + 1] - start;
        for (int base = 0; base < cnt; base += 32) {
            int rem = cnt - base;
            int m   = rem < 32 ? rem : 32;
            int c   = (lane < m) ? g_col[start + base + lane] : 0;
            int t = 0;
            for (; t + 4 <= m; t += 4) {
                int s0 = __shfl_sync(0xffffffffu, c, t);
                int s1 = __shfl_sync(0xffffffffu, c, t + 1);
                int s2 = __shfl_sync(0xffffffffu, c, t + 2);
                int s3 = __shfl_sync(0xffffffffu, c, t + 3);
                float2 v0 = xs[s0 * 32 + lane];
                float2 v1 = xs[s1 * 32 + lane];
                float2 v2 = xs[s2 * 32 + lane];
                float2 v3 = xs[s3 * 32 + lane];
                a0 += v0.x; a1 += v0.y;
                a0 += v1.x; a1 += v1.y;
                a0 += v2.x; a1 += v2.y;
                a0 += v3.x; a1 += v3.y;
            }
            for (; t < m; t++) {
                int s = __shfl_sync(0xffffffffu, c, t);
                float2 vv = xs[s * 32 + lane];
                a0 += vv.x; a1 += vv.y;
            }
        }
        float inv = 1.0f / (float)(cnt + 1);
        a_s[nl * PAD + 2 * lane]     = a0 * inv;
        a_s[nl * PAD + 2 * lane + 1] = a1 * inv;
    }
    __syncthreads();

    // GEMM: 2 nodes x 8 feats per thread
    const int nrow = (tid >> 3) << 1;   // 0,2,...,126
    const int fcol = (tid & 7) << 3;    // 0,8,...,56

    float acc[2][8];
    #pragma unroll
    for (int i = 0; i < 2; i++)
        #pragma unroll
        for (int f = 0; f < 8; f++) acc[i][f] = 0.f;

    #pragma unroll 8
    for (int kk = 0; kk < DIM; kk++) {
        float wlv[8], wrv[8];
        *(float4*)&wlv[0] = *(const float4*)&wl_s[kk * DIM + fcol];
        *(float4*)&wlv[4] = *(const float4*)&wl_s[kk * DIM + fcol + 4];
        *(float4*)&wrv[0] = *(const float4*)&wr_s[kk * DIM + fcol];
        *(float4*)&wrv[4] = *(const float4*)&wr_s[kk * DIM + fcol + 4];
        #pragma unroll
        for (int i = 0; i < 2; i++) {
            float av = a_s[(nrow + i) * PAD + kk];
            float xv = x_s[(nrow + i) * PAD + kk];
            #pragma unroll
            for (int f = 0; f < 8; f++)
                acc[i][f] += av * wlv[f] + xv * wrv[f];
        }
    }

    float bv[8];
    *(float4*)&bv[0] = *(const float4*)(bl + fcol);
    *(float4*)&bv[4] = *(const float4*)(bl + fcol + 4);

    #pragma unroll
    for (int i = 0; i < 2; i++) {
        int node = node0 + nrow + i;
        if (node < N_NODES) {
            float4 o0, o1;
            o0.x = fmaxf(acc[i][0] + bv[0], 0.f);
            o0.y = fmaxf(acc[i][1] + bv[1], 0.f);
            o0.z = fmaxf(acc[i][2] + bv[2], 0.f);
            o0.w = fmaxf(acc[i][3] + bv[3], 0.f);
            o1.x = fmaxf(acc[i][4] + bv[4], 0.f);
            o1.y = fmaxf(acc[i][5] + bv[5], 0.f);
            o1.z = fmaxf(acc[i][6] + bv[6], 0.f);
            o1.w = fmaxf(acc[i][7] + bv[7], 0.f);
            *(float4*)(out + node * DIM + fcol)     = o0;
            *(float4*)(out + node * DIM + fcol + 4) = o1;
        }
    }
}

// ------------------------------------------------------------------ launch
extern "C" void kernel_launch(void* const* d_in, const int* in_sizes, int n_in,
                              void* d_out, int out_size) {
    const float* x   = (const float*)d_in[0];
    const int*   ei  = (const int*)  d_in[1];
    const float* Wl0 = (const float*)d_in[2];
    const float* bl0 = (const float*)d_in[3];
    const float* Wr0 = (const float*)d_in[4];
    const float* Wl1 = (const float*)d_in[5];
    const float* bl1 = (const float*)d_in[6];
    const float* Wr1 = (const float*)d_in[7];
    float* out = (float*)d_out;

    const int LAYER_SMEM = (8192 + 2 * 128 * PAD) * sizeof(float);  // 99328 B
    cudaFuncSetAttribute(k_layer, cudaFuncAttributeMaxDynamicSharedMemorySize,
                         LAYER_SMEM);

    int layer_blocks  = (N_NODES + 127) / 128;
    int edge4_blocks  = (N_EDGES / 4 + 255) / 256;

    k_hist      <<<edge4_blocks, 256>>>(ei);                                  // 1
    k_scan_chain<<<NCHUNK, 1024>>>();                                         // 2
    k_scatter   <<<edge4_blocks, 256>>>(ei);                                  // 3
    k_layer     <<<layer_blocks, 512, LAYER_SMEM>>>(x,    Wl0, bl0, Wr0, g_x1); // 4 <- ncu
    k_layer     <<<layer_blocks, 512, LAYER_SMEM>>>(g_x1, Wl1, bl1, Wr1, out);  // 5
}